// round 17
// baseline (speedup 1.0000x reference)
#include <cuda_runtime.h>
#include <cuda_fp16.h>
#include <cstdint>

// z: [32,256,32,32] f32; emb: [1024,256] f32
// out: [8388608 z_q_st][32768 idx-as-f32][1 loss] f32

#define CQ      256
#define HWQ     1024
#define NPX     32768
#define KQ      1024
#define ZQ_ELEMS 8388608
#define NUNITS  2048
#define NWORK   296
#define HM      5e-3f        // margin in m = (dot - en2/2) space
#define CCAP    20

typedef unsigned long long u64;

// ---- device scratch (no allocations allowed) ----
__device__ float g_en2[KQ];
__device__ float g_zn2[NPX];
__device__ __half g_zh[ZQ_ELEMS];       // fp16 z, same [b][c][hw] layout
__device__ __half g_ebT[CQ * KQ];       // fp16 emb TRANSPOSED [c][k]
__device__ int   g_cand[NPX * CCAP];
__device__ int   g_ccnt[NPX];
__device__ int   g_idx[NPX];
__device__ float g_part[1024];
__device__ int   g_unit;
__device__ int   g_done;

// ---------------------------------------------------------------------------
// Kernel 1: blocks 0-7 -> ||e||^2 + fp16 emb transpose; blocks 8-263 ->
// ||z||^2 (2-way split, proven argmin-safe) + g_ccnt reset. Resets counters.
// ---------------------------------------------------------------------------
__global__ void vq_pre(const float* __restrict__ emb, const float* __restrict__ z) {
    int t = threadIdx.x;
    if (blockIdx.x == 0 && t == 0) { g_unit = 0; g_done = 0; }
    if (blockIdx.x < 8) {
        int warp = (blockIdx.x * blockDim.x + t) >> 5;
        int lane = t & 31;
        for (int i = 0; i < 16; i++) {
            int k = warp * 16 + i;
            const float* row = emb + (long)k * CQ;
            float s = 0.0f;
            #pragma unroll
            for (int j = 0; j < 8; j++) {
                float v = row[lane + 32 * j];
                g_ebT[(lane + 32 * j) * KQ + k] = __float2half(v);
                s = __fadd_rn(s, __fmul_rn(v, v));
            }
            #pragma unroll
            for (int off = 16; off; off >>= 1)
                s = __fadd_rn(s, __shfl_xor_sync(0xffffffffu, s, off));
            if (lane == 0) g_en2[k] = s;
        }
    } else {
        __shared__ float sh[256];
        int pxl = t & 127, half = t >> 7;
        int n = (blockIdx.x - 8) * 128 + pxl;
        int bb = n >> 10, hw = n & 1023;
        const float* p = z + ((long)bb << 18) + hw + ((long)(half * 128) << 10);
        float acc = 0.0f;
        #pragma unroll 16
        for (int c = 0; c < 128; c++) {
            float v = p[(long)c << 10];
            acc = fmaf(v, v, acc);
        }
        sh[t] = acc;
        __syncthreads();
        if (half == 0) {
            g_zn2[n] = __fadd_rn(sh[t], sh[t + 128]);
            g_ccnt[n] = 0;
        }
    }
}

// ---------------------------------------------------------------------------
// Kernel 2: z fp32 -> fp16 elementwise (layout-preserving).
// ---------------------------------------------------------------------------
__global__ __launch_bounds__(256) void vq_zh(const float* __restrict__ z) {
    long base = ((long)blockIdx.x * 256 + threadIdx.x) * 16;
    #pragma unroll
    for (int i = 0; i < 4; i++) {
        float4 v = *(const float4*)(z + base + i * 4);
        __half2 h0 = __floats2half2_rn(v.x, v.y);
        __half2 h1 = __floats2half2_rn(v.z, v.w);
        *(__half2*)(g_zh + base + i * 4)     = h0;
        *(__half2*)(g_zh + base + i * 4 + 2) = h1;
    }
}

// ---------------------------------------------------------------------------
// Kernel 3: persistent HFMA2 approx screen + candidate selection.
// Unit = (64px tile, 256-code block). half2 lanes = 2 adjacent pixels.
// z tile [64c][64px] fp16 (row 144B), eT tile [64c][256k] fp16 (row 528B),
// both direct cp.async (no transposes). acc = 256 fused fp16 adds.
// Two-pass register-lean epilogue: local max -> margin -> candidates.
// ---------------------------------------------------------------------------
#define ZB0 0
#define ZB1 9216
#define EB0 18432
#define EB1 52224
#define EN2S 86016
#define RMS_OFF 87040
#define SMEM_BYTES 87552

__device__ __forceinline__ void cpasync16(uint32_t dst, const void* src) {
    asm volatile("cp.async.cg.shared.global [%0], [%1], 16;" :: "r"(dst), "l"(src));
}

__global__ void __launch_bounds__(256, 2)
vq_hfma(int dummy) {
    extern __shared__ __align__(16) char smc[];
    uint32_t smb = (uint32_t)__cvta_generic_to_shared(smc);
    float* en2s = (float*)(smc + EN2S);
    float* rmS  = (float*)(smc + RMS_OFF);
    float* redv = (float*)smc;              // reuses z/e buffers post-compute
    __shared__ int s_u;

    const int t  = threadIdx.x;
    const int pg = t & 7;
    const int kg = t >> 3;                  // 0..31 -> codes kg*8..kg*8+7
    const int pxA = pg * 4;
    const int pxB = 32 + pg * 4;

    while (true) {
        __syncthreads();
        if (t == 0) s_u = atomicAdd(&g_unit, 1);
        __syncthreads();
        int u = s_u;
        if (u >= NUNITS) break;

        const int tile = u >> 2;
        const int kb   = (u & 3) << 8;
        const int bb   = tile >> 4;
        const int hw0  = (tile & 15) << 6;
        const __half* zb_g = g_zh + ((long)bb << 18) + hw0;

        en2s[t] = 0.5f * g_en2[kb + t];

        __half2 acc[4][8];
        #pragma unroll
        for (int pp = 0; pp < 4; pp++)
            #pragma unroll
            for (int j = 0; j < 8; j++) acc[pp][j] = __floats2half2_rn(0.f, 0.f);

        // fill stage 0
        {
            #pragma unroll
            for (int i = 0; i < 2; i++) {           // z: 64c x 128B
                int idx = t + (i << 8);
                int row = idx >> 3, q = idx & 7;
                cpasync16(smb + ZB0 + row * 144 + q * 16,
                          zb_g + (long)row * HWQ + q * 8);
            }
            #pragma unroll
            for (int i = 0; i < 8; i++) {           // e: 64c x 512B
                int idx = t + (i << 8);
                int row = idx >> 5, q = idx & 31;
                cpasync16(smb + EB0 + row * 528 + q * 16,
                          g_ebT + (long)row * KQ + kb + q * 8);
            }
            asm volatile("cp.async.commit_group;" ::: "memory");
        }

        for (int s = 0; s < 4; s++) {
            asm volatile("cp.async.wait_group 0;" ::: "memory");
            __syncthreads();
            if (s < 3) {
                int cb = (s + 1) << 6, b = (s + 1) & 1;
                #pragma unroll
                for (int i = 0; i < 2; i++) {
                    int idx = t + (i << 8);
                    int row = idx >> 3, q = idx & 7;
                    cpasync16(smb + (b ? ZB1 : ZB0) + row * 144 + q * 16,
                              zb_g + (long)(cb + row) * HWQ + q * 8);
                }
                #pragma unroll
                for (int i = 0; i < 8; i++) {
                    int idx = t + (i << 8);
                    int row = idx >> 5, q = idx & 31;
                    cpasync16(smb + (b ? EB1 : EB0) + row * 528 + q * 16,
                              g_ebT + (long)(cb + row) * KQ + kb + q * 8);
                }
                asm volatile("cp.async.commit_group;" ::: "memory");
            }
            const int zoff = (s & 1) ? ZB1 : ZB0;
            const int eoff = (s & 1) ? EB1 : EB0;
            #pragma unroll 2
            for (int c = 0; c < 64; c++) {
                const __half2* zr = (const __half2*)(smc + zoff + c * 144);
                __half2 za0 = zr[pg * 2], za1 = zr[pg * 2 + 1];
                __half2 zb0 = zr[16 + pg * 2], zb1 = zr[16 + pg * 2 + 1];
                uint4 ew = *(const uint4*)(smc + eoff + c * 528 + kg * 16);
                const __half2* eh = (const __half2*)&ew;
                #pragma unroll
                for (int j = 0; j < 8; j++) {
                    __half ej = (j & 1) ? __high2half(eh[j >> 1]) : __low2half(eh[j >> 1]);
                    __half2 e2 = __half2half2(ej);
                    acc[0][j] = __hfma2(za0, e2, acc[0][j]);
                    acc[1][j] = __hfma2(za1, e2, acc[1][j]);
                    acc[2][j] = __hfma2(zb0, e2, acc[2][j]);
                    acc[3][j] = __hfma2(zb1, e2, acc[3][j]);
                }
            }
        }

        // ---- epilogue pass 1: per-pixel max of m = dot - en2/2 over the unit
        float mx[8];
        #pragma unroll
        for (int i = 0; i < 8; i++) mx[i] = -3.4e38f;
        #pragma unroll
        for (int j = 0; j < 8; j++) {
            float ev = en2s[kg * 8 + j];
            #pragma unroll
            for (int pp = 0; pp < 4; pp++) {
                float2 f = __half22float2(acc[pp][j]);
                mx[pp * 2]     = fmaxf(mx[pp * 2],     f.x - ev);
                mx[pp * 2 + 1] = fmaxf(mx[pp * 2 + 1], f.y - ev);
            }
        }
        __syncthreads();                    // z/e buffers free -> redv
        // slot s: pp = s>>1, lane = s&1 -> px mapping
        #pragma unroll
        for (int s2 = 0; s2 < 8; s2++) {
            int px = ((s2 >> 2) ? pxB : pxA) + ((s2 >> 1) & 1) * 2 + (s2 & 1);
            redv[kg * 64 + px] = mx[s2];
        }
        __syncthreads();
        if (t < 64) {
            float bv = redv[t];
            #pragma unroll 4
            for (int g = 1; g < 32; g++) bv = fmaxf(bv, redv[g * 64 + t]);
            rmS[t] = bv;
        }
        __syncthreads();
        // ---- pass 2: candidates (recompute m from live acc)
        #pragma unroll
        for (int j = 0; j < 8; j++) {
            float ev = en2s[kg * 8 + j];
            int code = kb + kg * 8 + j;
            #pragma unroll
            for (int pp = 0; pp < 4; pp++) {
                float2 f = __half22float2(acc[pp][j]);
                #pragma unroll
                for (int h = 0; h < 2; h++) {
                    float m = (h ? f.y : f.x) - ev;
                    int px = ((pp >> 1) ? pxB : pxA) + (pp & 1) * 2 + h;
                    if (m > rmS[px] - HM) {
                        int n = tile * 64 + px;
                        int pos = atomicAdd(&g_ccnt[n], 1);
                        if (pos < CCAP) g_cand[(long)n * CCAP + pos] = code;
                    }
                }
            }
        }
    }
}

// ---------------------------------------------------------------------------
// Kernel 4: exact rescore (reference-bit-exact fold, proven in R10):
// d = fl( fl(zn2 + en2) - fl(2*dot) ), ascending-c fmaf dot, tie -> lowest.
// Overflowed candidate lists fall back to a full exact scan.
// ---------------------------------------------------------------------------
__global__ __launch_bounds__(256) void vq_exact(const float* __restrict__ z,
                                                const float* __restrict__ emb,
                                                float* __restrict__ out_idx) {
    int n = blockIdx.x * 256 + threadIdx.x;
    int bb = n >> 10, hw = n & 1023;
    const float* zp = z + ((long)bb << 18) + hw;
    float zn2 = g_zn2[n];

    int cnt = g_ccnt[n];
    bool full = (cnt > CCAP);
    if (full) cnt = 0;
    float bv = 3.402823466e38f;
    int bi = 0x7fffffff;
    for (int j = 0; j < cnt; j++) {
        int k = g_cand[(long)n * CCAP + j];
        const float* er = emb + (long)k * CQ;
        float dot = 0.0f;
        #pragma unroll 8
        for (int c = 0; c < CQ; c++) dot = fmaf(zp[(long)c << 10], er[c], dot);
        float v = __fadd_rn(__fadd_rn(zn2, g_en2[k]), __fmul_rn(-2.0f, dot));
        if (v < bv || (v == bv && k < bi)) { bv = v; bi = k; }
    }
    if (full) {
        for (int k = 0; k < KQ; k++) {
            const float* er = emb + (long)k * CQ;
            float dot = 0.0f;
            #pragma unroll 8
            for (int c = 0; c < CQ; c++) dot = fmaf(zp[(long)c << 10], er[c], dot);
            float v = __fadd_rn(__fadd_rn(zn2, g_en2[k]), __fmul_rn(-2.0f, dot));
            if (v < bv || (v == bv && k < bi)) { bv = v; bi = k; }
        }
    }
    g_idx[n] = bi;
    out_idx[n] = (float)bi;
}

// ---------------------------------------------------------------------------
// Kernel 5: gather + STE + loss (R15 version, fused final reduction).
// ---------------------------------------------------------------------------
#define GSTR 259
__global__ __launch_bounds__(256) void vq_gather(const float* __restrict__ z,
                                                 const float* __restrict__ emb,
                                                 float* __restrict__ outz,
                                                 float* __restrict__ out_all) {
    extern __shared__ float srows[];           // [32][GSTR]
    __shared__ int idxs[32];
    __shared__ float ws[8];
    __shared__ int lastflag;
    int t = threadIdx.x, blk = blockIdx.x;
    int bb = blk >> 5, hw0 = (blk & 31) << 5;

    if (t < 32) idxs[t] = g_idx[blk * 32 + t];
    __syncthreads();
    {
        int r = t >> 3, part = t & 7;
        const float4* er = (const float4*)(emb + (long)idxs[r] * CQ);
        float* d = srows + r * GSTR;
        #pragma unroll
        for (int i = 0; i < 8; i++) {
            float4 v = er[part + i * 8];
            int c = (part + i * 8) * 4;
            d[c] = v.x; d[c + 1] = v.y; d[c + 2] = v.z; d[c + 3] = v.w;
        }
    }
    __syncthreads();
    int px = t & 31, c0 = t >> 5;
    const float* zb = z + ((long)bb << 18) + hw0;
    float* ob = outz + ((long)bb << 18) + hw0;
    float acc = 0.0f;
    #pragma unroll 8
    for (int i = 0; i < 32; i++) {
        int c = i * 8 + c0;
        float zv = zb[(long)c * HWQ + px];
        float qv = srows[px * GSTR + c];
        float d0 = __fadd_rn(qv, -zv);
        ob[(long)c * HWQ + px] = __fadd_rn(zv, d0);     // == z + sg(z_q - z)
        acc = fmaf(d0, d0, acc);
    }
    #pragma unroll
    for (int off = 16; off; off >>= 1)
        acc += __shfl_xor_sync(0xffffffffu, acc, off);
    if ((t & 31) == 0) ws[t >> 5] = acc;
    __syncthreads();
    if (t == 0) {
        float tot = 0.0f;
        #pragma unroll
        for (int i = 0; i < 8; i++) tot += ws[i];
        g_part[blk] = tot;
        __threadfence();
        lastflag = (atomicAdd(&g_done, 1) == 1023);
    }
    __syncthreads();
    if (lastflag) {
        __shared__ double red[256];
        double s = 0.0;
        for (int i = t; i < 1024; i += 256) s += (double)g_part[i];
        red[t] = s;
        __syncthreads();
        for (int st = 128; st; st >>= 1) {
            if (t < st) red[t] += red[t + st];
            __syncthreads();
        }
        if (t == 0) {
            float m = (float)(red[0] / 8388608.0);
            out_all[ZQ_ELEMS + NPX] = 0.25f * m + m;
        }
    }
}

// ---------------------------------------------------------------------------
extern "C" void kernel_launch(void* const* d_in, const int* in_sizes, int n_in,
                              void* d_out, int out_size) {
    const float* z   = (const float*)d_in[0];
    const float* emb = (const float*)d_in[1];
    float* out = (float*)d_out;

    cudaFuncSetAttribute(vq_hfma, cudaFuncAttributeMaxDynamicSharedMemorySize,
                         SMEM_BYTES);
    cudaFuncSetAttribute(vq_gather, cudaFuncAttributeMaxDynamicSharedMemorySize,
                         32 * GSTR * 4);

    vq_pre<<<264, 256>>>(emb, z);
    vq_zh<<<2048, 256>>>(z);
    vq_hfma<<<NWORK, 256, SMEM_BYTES>>>(0);
    vq_exact<<<128, 256>>>(z, emb, out + ZQ_ELEMS);
    vq_gather<<<1024, 256, 32 * GSTR * 4>>>(z, emb, out, out);
}